// round 8
// baseline (speedup 1.0000x reference)
#include <cuda_runtime.h>
#include <cuda_bf16.h>
#include <stdint.h>
#include <math.h>

#define Bn 128
#define Ln 1024
#define Vn 32
#define En 256
#define Hn 1024
#define NTOT 1056            // Hn + Vn (W_o folded)
#define NPAD 1088            // padded to 17*64

#define KSP 8                // K splits
#define KSL 128              // K per CTA
#define NTL 17               // N tiles
#define NSL 64               // N cols per CTA
#define G   (KSP * NTL)      // 136 persistent CTAs
#define NT  512
#define PK  136              // smem k-pitch (bf16); 272B row stride -> LDSM conflict-free
#define FP  8                // flag padding (words): one flag per 32B sector

// ---------------- device scratch ----------------
__device__ float         g_P[Vn * Hn];
__device__ __nv_bfloat16 g_hbf_hi[2][Bn * Hn];
__device__ __nv_bfloat16 g_hbf_lo[2][Bn * Hn];
__device__ __nv_bfloat16 g_WT_hi[NPAD * Hn];   // [n][k]; n<1024 WhT, 1024..1055 WoT, rest 0
__device__ __nv_bfloat16 g_WT_lo[NPAD * Hn];
__device__ float         g_part[KSP][Bn][NPAD];
__device__ unsigned      g_flag1[G * FP];      // barrier-1 flags (all G arrive)
__device__ unsigned      g_flag2[Bn * FP];     // barrier-2 flags (Bn producers arrive)

// smem: sAhi[128][PK], sAlo[128][PK], sBhi[64][PK], sBlo[64][PK] (bf16) = 104448 B
#define SMEM_BYTES ((128 * PK * 2 + 64 * PK * 2) * 2)

// ---------------- helpers ----------------
#define MMA16816(d, a0, a1, a2, a3, b0, b1) \
    asm volatile("mma.sync.aligned.m16n8k16.row.col.f32.bf16.bf16.f32 " \
        "{%0,%1,%2,%3}, {%4,%5,%6,%7}, {%8,%9}, {%0,%1,%2,%3};" \
        : "+f"((d)[0]), "+f"((d)[1]), "+f"((d)[2]), "+f"((d)[3]) \
        : "r"(a0), "r"(a1), "r"(a2), "r"(a3), "r"(b0), "r"(b1))

#define LDSM4(r0, r1, r2, r3, addr) \
    asm volatile("ldmatrix.sync.aligned.m8n8.x4.shared.b16 {%0,%1,%2,%3}, [%4];" \
        : "=r"(r0), "=r"(r1), "=r"(r2), "=r"(r3) : "r"(addr))

__device__ __forceinline__ uint32_t smem_u32(const void* p) {
    uint32_t a;
    asm("{ .reg .u64 t; cvta.to.shared.u64 t, %1; cvt.u32.u64 %0, t; }"
        : "=r"(a) : "l"(p));
    return a;
}
__device__ __forceinline__ unsigned acqload(const unsigned* p) {
    unsigned v;
    asm volatile("ld.acquire.gpu.u32 %0, [%1];" : "=r"(v) : "l"(p) : "memory");
    return v;
}
__device__ __forceinline__ void relstore(unsigned* p, unsigned v) {
    asm volatile("st.release.gpu.u32 [%0], %1;" :: "l"(p), "r"(v) : "memory");
}
__device__ __forceinline__ uint4 ldcg4(const void* p) {
    uint4 r;
    asm volatile("ld.global.cg.v4.u32 {%0,%1,%2,%3}, [%4];"
        : "=r"(r.x), "=r"(r.y), "=r"(r.z), "=r"(r.w) : "l"(p));
    return r;
}
__device__ __forceinline__ float2 ldcg2f(const void* p) {
    float2 r;
    asm volatile("ld.global.cg.v2.f32 {%0,%1}, [%2];"
        : "=f"(r.x), "=f"(r.y) : "l"(p));
    return r;
}
__device__ __forceinline__ float ldcgf(const void* p) {
    float r;
    asm volatile("ld.global.cg.f32 %0, [%1];" : "=f"(r) : "l"(p));
    return r;
}
__device__ __forceinline__ void pack_hilo(float v, unsigned short& hi, unsigned short& lo) {
    __nv_bfloat16 hb = __float2bfloat16(v);
    hi = __bfloat16_as_ushort(hb);
    lo = __bfloat16_as_ushort(__float2bfloat16(v - __bfloat162float(hb)));
}
__device__ __forceinline__ float fast_tanh(float x) {
    // tanh(x) = 1 - 2/(e^{2x}+1); saturates correctly for |x| large
    float e = __expf(2.0f * x);
    return 1.0f - __fdividef(2.0f, e + 1.0f);
}

// ---------------- the single persistent kernel ----------------
__global__ void __launch_bounds__(NT, 1)
rnn_all(const int* __restrict__ x, const float* __restrict__ hidden,
        const float* __restrict__ emb, const float* __restrict__ We,
        const float* __restrict__ Wh, const float* __restrict__ bh,
        const float* __restrict__ Wo, const float* __restrict__ bo,
        float* __restrict__ logits, float* __restrict__ outh) {
    extern __shared__ __align__(16) char dsm[];
    __nv_bfloat16* sAhi = (__nv_bfloat16*)dsm;
    __nv_bfloat16* sAlo = sAhi + 128 * PK;
    __nv_bfloat16* sBhi = sAlo + 128 * PK;
    __nv_bfloat16* sBlo = sBhi + 64 * PK;

    const int tid = threadIdx.x, bid = blockIdx.x;
    const int kt  = bid / NTL;          // 0..7
    const int ntl = bid % NTL;          // 0..16
    const int lane = tid & 31, w = tid >> 5;     // 16 warps
    const int gq = lane >> 2, tg = lane & 3;
    const int m0 = (w >> 1) * 16;       // 8 m-groups of 16 rows
    const int nh = w & 1;               // n-half: 32 cols each

    // monotonic token bases (flags quiescent & equal at launch)
    unsigned tok1 = acqload(&g_flag1[bid * FP]);
    unsigned tok2 = acqload(&g_flag2[(bid & (Bn - 1)) * FP]);

    // ======== prologue ========
    for (int k2 = tid; k2 < Hn; k2 += NT) {
#pragma unroll
        for (int j = 0; j < 8; ++j) {
            int n = bid * 8 + j;
            float wv = 0.f;
            if (n < Hn)            wv = Wh[k2 * Hn + n];
            else if (n < NTOT)     wv = Wo[k2 * Vn + (n - Hn)];
            unsigned short hi, lo; pack_hilo(wv, hi, lo);
            g_WT_hi[n * Hn + k2] = __ushort_as_bfloat16(hi);
            g_WT_lo[n * Hn + k2] = __ushort_as_bfloat16(lo);
        }
    }
    {
        int e = bid * NT + tid;
        if (e < Vn * Hn) {
            int v = e >> 10, h = e & 1023;
            float acc = bh[h];
            const float* er = emb + v * En;
#pragma unroll 8
            for (int q = 0; q < En; ++q) acc = fmaf(er[q], We[q * Hn + h], acc);
            g_P[e] = acc;
        }
    }
    if (bid < Bn) {
        int i0 = bid * Hn + tid * 2;
        float2 hv = *(const float2*)(hidden + i0);
        unsigned short h0u, l0u, h1u, l1u;
        pack_hilo(hv.x, h0u, l0u); pack_hilo(hv.y, h1u, l1u);
        *(uint32_t*)(&g_hbf_hi[0][i0]) = (uint32_t)h0u | ((uint32_t)h1u << 16);
        *(uint32_t*)(&g_hbf_lo[0][i0]) = (uint32_t)l0u | ((uint32_t)l1u << 16);
    }
    // prologue barrier: all G via flag1
    __syncthreads();
    ++tok1;
    if (tid == 0) relstore(&g_flag1[bid * FP], tok1);
    if (tid < G) {
        const unsigned* p = &g_flag1[tid * FP];
        while ((int)(acqload(p) - tok1) < 0) {}
    }
    __syncthreads();

    // persistent B tile -> smem
    for (int idx = tid; idx < NSL * KSL; idx += NT) {
        int n = idx >> 7, k = idx & 127;
        int src = (ntl * NSL + n) * Hn + kt * KSL + k;
        sBhi[n * PK + k] = g_WT_hi[src];
        sBlo[n * PK + k] = g_WT_lo[src];
    }

    // fragment base addresses
    const uint32_t aBaseHi = smem_u32(sAhi) +
        (uint32_t)(((m0 + (lane & 7) + ((lane >> 3) & 1) * 8) * PK + (lane >> 4) * 8) * 2);
    const uint32_t aBaseLo = aBaseHi + (uint32_t)(128 * PK * 2);
    const int nl0 = (nh * 4 + 0 + (lane >> 4)) * 8 + (lane & 7);
    const int nl1 = (nh * 4 + 2 + (lane >> 4)) * 8 + (lane & 7);
    const int bko = ((lane >> 3) & 1) * 8;
    const uint32_t bBaseHi0 = smem_u32(sBhi) + (uint32_t)((nl0 * PK + bko) * 2);
    const uint32_t bBaseHi1 = smem_u32(sBhi) + (uint32_t)((nl1 * PK + bko) * 2);
    const uint32_t bBaseLo0 = bBaseHi0 + (uint32_t)(64 * PK * 2);
    const uint32_t bBaseLo1 = bBaseHi1 + (uint32_t)(64 * PK * 2);

    // ======== recurrence: iter l consumes h_l -> partials(h_{l+1}, logits_{l-1}) ========
    for (int l = 0; l <= Ln; ++l) {
        const int c = l & 1;
        const bool doMMA = (l < Ln) || (ntl == NTL - 1);

        float acc[4][4];
#pragma unroll
        for (int nt = 0; nt < 4; ++nt)
#pragma unroll
            for (int q = 0; q < 4; ++q) acc[nt][q] = 0.f;

        uint4 lob[4];
        if (doMMA) {    // issue all A loads (hi then lo), commit hi to smem
            uint4 hib[4];
#pragma unroll
            for (int it = 0; it < 4; ++it) {
                int i = (it * NT + tid) * 8;
                int row = i >> 7, k = i & 127;
                hib[it] = ldcg4(&g_hbf_hi[c][row * Hn + kt * KSL + k]);
            }
#pragma unroll
            for (int it = 0; it < 4; ++it) {
                int i = (it * NT + tid) * 8;
                int row = i >> 7, k = i & 127;
                lob[it] = ldcg4(&g_hbf_lo[c][row * Hn + kt * KSL + k]);
            }
#pragma unroll
            for (int it = 0; it < 4; ++it) {
                int i = (it * NT + tid) * 8;
                int row = i >> 7, k = i & 127;
                *(uint4*)(sAhi + row * PK + k) = hib[it];
            }
        }
        __syncthreads();   // A-hi ready

        int xv = 0;
        if (bid < Bn && l < Ln) xv = __ldg(&x[bid * Ln + l]);

        if (doMMA) {
            // ---- A-hi terms: Ahi*Bhi + Ahi*Blo ----
#pragma unroll
            for (int kk = 0; kk < 8; ++kk) {
                const uint32_t ko = kk * 32;
                uint32_t ah0, ah1, ah2, ah3;
                LDSM4(ah0, ah1, ah2, ah3, aBaseHi + ko);
                uint32_t b00, b01, b10, b11, b20, b21, b30, b31;
                LDSM4(b00, b01, b10, b11, bBaseHi0 + ko);
                LDSM4(b20, b21, b30, b31, bBaseHi1 + ko);
                uint32_t c00, c01, c10, c11, c20, c21, c30, c31;
                LDSM4(c00, c01, c10, c11, bBaseLo0 + ko);
                LDSM4(c20, c21, c30, c31, bBaseLo1 + ko);
                MMA16816(acc[0], ah0, ah1, ah2, ah3, b00, b01);
                MMA16816(acc[1], ah0, ah1, ah2, ah3, b10, b11);
                MMA16816(acc[2], ah0, ah1, ah2, ah3, b20, b21);
                MMA16816(acc[3], ah0, ah1, ah2, ah3, b30, b31);
                MMA16816(acc[0], ah0, ah1, ah2, ah3, c00, c01);
                MMA16816(acc[1], ah0, ah1, ah2, ah3, c10, c11);
                MMA16816(acc[2], ah0, ah1, ah2, ah3, c20, c21);
                MMA16816(acc[3], ah0, ah1, ah2, ah3, c30, c31);
            }
            // commit A-lo
#pragma unroll
            for (int it = 0; it < 4; ++it) {
                int i = (it * NT + tid) * 8;
                int row = i >> 7, k = i & 127;
                *(uint4*)(sAlo + row * PK + k) = lob[it];
            }
        }
        __syncthreads();   // A-lo ready

        if (doMMA) {
            // ---- A-lo term: Alo*Bhi ----
#pragma unroll
            for (int kk = 0; kk < 8; ++kk) {
                const uint32_t ko = kk * 32;
                uint32_t al0, al1, al2, al3;
                LDSM4(al0, al1, al2, al3, aBaseLo + ko);
                uint32_t b00, b01, b10, b11, b20, b21, b30, b31;
                LDSM4(b00, b01, b10, b11, bBaseHi0 + ko);
                LDSM4(b20, b21, b30, b31, bBaseHi1 + ko);
                MMA16816(acc[0], al0, al1, al2, al3, b00, b01);
                MMA16816(acc[1], al0, al1, al2, al3, b10, b11);
                MMA16816(acc[2], al0, al1, al2, al3, b20, b21);
                MMA16816(acc[3], al0, al1, al2, al3, b30, b31);
            }
#pragma unroll
            for (int nt = 0; nt < 4; ++nt) {
                int col = ntl * NSL + (nh * 4 + nt) * 8 + tg * 2;
                *(float2*)(&g_part[kt][m0 + gq][col])     = make_float2(acc[nt][0], acc[nt][1]);
                *(float2*)(&g_part[kt][m0 + gq + 8][col]) = make_float2(acc[nt][2], acc[nt][3]);
            }
        }

        // prefetch P row entry for phase-2
        float2 Pv = make_float2(0.f, 0.f);
        if (bid < Bn && l < Ln)
            Pv = *(const float2*)(g_P + xv * Hn + tid * 2);

        // ---- barrier 1: partials ready (all arrive; phase-2 CTAs wait) ----
        __syncthreads();
        ++tok1;
        if (tid == 0) relstore(&g_flag1[bid * FP], tok1);

        if (bid < Bn) {
            if (tid < G) {
                const unsigned* p = &g_flag1[tid * FP];
                while ((int)(acqload(p) - tok1) < 0) {}
            }
            __syncthreads();
            const int b = bid;
            if (l < Ln) {
                const int h0 = tid * 2;
                float2 s = Pv;
#pragma unroll
                for (int j = 0; j < KSP; ++j) {
                    float2 p = ldcg2f(&g_part[j][b][h0]);
                    s.x += p.x; s.y += p.y;
                }
                float2 hv;
                hv.x = fast_tanh(s.x); hv.y = fast_tanh(s.y);
                unsigned short h0u, l0u, h1u, l1u;
                pack_hilo(hv.x, h0u, l0u); pack_hilo(hv.y, h1u, l1u);
                int i0 = b * Hn + h0;
                *(uint32_t*)(&g_hbf_hi[1 - c][i0]) = (uint32_t)h0u | ((uint32_t)h1u << 16);
                *(uint32_t*)(&g_hbf_lo[1 - c][i0]) = (uint32_t)l0u | ((uint32_t)l1u << 16);
                if (l == Ln - 1)
                    *(float2*)(outh + i0) = hv;
            }
            if (l > 0 && tid < Vn) {
                float s = bo[tid];
#pragma unroll
                for (int j = 0; j < KSP; ++j) s += ldcgf(&g_part[j][b][Hn + tid]);
                logits[((size_t)b * Ln + (l - 1)) * Vn + tid] = s;
            }
            __syncthreads();
            if (tid == 0) relstore(&g_flag2[bid * FP], tok2 + 1);
        }
        ++tok2;

        // ---- barrier 2: new h ready (everyone waits) ----
        if (l < Ln) {
            if (tid < Bn) {
                const unsigned* p = &g_flag2[tid * FP];
                while ((int)(acqload(p) - tok2) < 0) {}
            }
            __syncthreads();
        }
    }
}

extern "C" void kernel_launch(void* const* d_in, const int* in_sizes, int n_in,
                              void* d_out, int out_size) {
    const int*   x      = (const int*)d_in[0];
    const float* hidden = (const float*)d_in[1];
    const float* emb    = (const float*)d_in[2];
    const float* We     = (const float*)d_in[3];
    const float* Wh     = (const float*)d_in[4];
    const float* bh     = (const float*)d_in[5];
    const float* Wo     = (const float*)d_in[6];
    const float* bo     = (const float*)d_in[7];

    float* logits = (float*)d_out;
    float* outh   = logits + (size_t)Bn * Ln * Vn;

    cudaFuncSetAttribute(rnn_all,
                         cudaFuncAttributeMaxDynamicSharedMemorySize, SMEM_BYTES);
    rnn_all<<<G, NT, SMEM_BYTES>>>(x, hidden, emb, We, Wh, bh, Wo, bo, logits, outh);
}

// round 9
// speedup vs baseline: 1.5166x; 1.5166x over previous
#include <cuda_runtime.h>
#include <cuda_bf16.h>
#include <stdint.h>
#include <math.h>

#define Bn 128
#define Ln 1024
#define Vn 32
#define En 256
#define Hn 1024
#define NTOT 1056        // Hn + Vn (W_o folded)

#define NG  4            // independent batch groups
#define BG  32           // batch rows per group
#define NTL 33           // CTAs per group (32 h-tiles + 1 logits tile)
#define NSL 32           // N cols per CTA
#define G   (NG * NTL)   // 132 persistent CTAs
#define NT  256
#define PA  520          // A smem pitch (bf16): 1040B rows -> LDSM conflict-free
#define PB  1032         // B smem pitch: 2064B rows -> LDSM conflict-free
#define KH  512          // K half

// ---------------- device scratch ----------------
__device__ float         g_P[Vn * Hn];
__device__ __nv_bfloat16 g_hbf_hi[2][Bn * Hn];
__device__ __nv_bfloat16 g_hbf_lo[2][Bn * Hn];
__device__ __nv_bfloat16 g_WT_hi[NTOT * Hn];   // [n][k]
__device__ __nv_bfloat16 g_WT_lo[NTOT * Hn];
__device__ unsigned      g_cnt_all;            // prologue barrier (all G)
__device__ unsigned      g_cntg[NG * 8];       // per-group step counters (padded)

// smem layout (bytes):
//  sBhi: 0             .. 66048
//  sBlo: 66048         .. 132096
//  sAhi: 132096        .. 165376
//  sAlo: 165376        .. 198656
//  sX  : 198656        .. 198784
#define OFF_BLO 66048
#define OFF_AHI 132096
#define OFF_ALO 165376
#define OFF_X   198656
#define SMEM_BYTES 198784

// ---------------- helpers ----------------
#define MMA16816(d, a0, a1, a2, a3, b0, b1) \
    asm volatile("mma.sync.aligned.m16n8k16.row.col.f32.bf16.bf16.f32 " \
        "{%0,%1,%2,%3}, {%4,%5,%6,%7}, {%8,%9}, {%0,%1,%2,%3};" \
        : "+f"((d)[0]), "+f"((d)[1]), "+f"((d)[2]), "+f"((d)[3]) \
        : "r"(a0), "r"(a1), "r"(a2), "r"(a3), "r"(b0), "r"(b1))

#define LDSM4(r0, r1, r2, r3, addr) \
    asm volatile("ldmatrix.sync.aligned.m8n8.x4.shared.b16 {%0,%1,%2,%3}, [%4];" \
        : "=r"(r0), "=r"(r1), "=r"(r2), "=r"(r3) : "r"(addr))

__device__ __forceinline__ uint32_t smem_u32(const void* p) {
    uint32_t a;
    asm("{ .reg .u64 t; cvta.to.shared.u64 t, %1; cvt.u32.u64 %0, t; }"
        : "=r"(a) : "l"(p));
    return a;
}
__device__ __forceinline__ unsigned acqload(const unsigned* p) {
    unsigned v;
    asm volatile("ld.acquire.gpu.u32 %0, [%1];" : "=r"(v) : "l"(p) : "memory");
    return v;
}
__device__ __forceinline__ void arrive(unsigned* cnt) {
    asm volatile("red.release.gpu.global.add.u32 [%0], 1;" :: "l"(cnt) : "memory");
}
__device__ __forceinline__ void waitcnt(unsigned* cnt, unsigned target) {
    unsigned v = acqload(cnt);
    while ((int)(v - target) < 0) v = acqload(cnt);
}
__device__ __forceinline__ uint4 ldcg4(const void* p) {
    uint4 r;
    asm volatile("ld.global.cg.v4.u32 {%0,%1,%2,%3}, [%4];"
        : "=r"(r.x), "=r"(r.y), "=r"(r.z), "=r"(r.w) : "l"(p));
    return r;
}
__device__ __forceinline__ void pack_hilo(float v, unsigned short& hi, unsigned short& lo) {
    __nv_bfloat16 hb = __float2bfloat16(v);
    hi = __bfloat16_as_ushort(hb);
    lo = __bfloat16_as_ushort(__float2bfloat16(v - __bfloat162float(hb)));
}
__device__ __forceinline__ float fast_tanh(float x) {
    float e = __expf(2.0f * x);
    return 1.0f - __fdividef(2.0f, e + 1.0f);
}

// ---------------- the single persistent kernel ----------------
__global__ void __launch_bounds__(NT, 1)
rnn_all(const int* __restrict__ x, const float* __restrict__ hidden,
        const float* __restrict__ emb, const float* __restrict__ We,
        const float* __restrict__ Wh, const float* __restrict__ bh,
        const float* __restrict__ Wo, const float* __restrict__ bo,
        float* __restrict__ logits, float* __restrict__ outh) {
    extern __shared__ __align__(16) char dsm[];
    __nv_bfloat16* sBhi = (__nv_bfloat16*)dsm;
    __nv_bfloat16* sBlo = (__nv_bfloat16*)(dsm + OFF_BLO);
    __nv_bfloat16* sAhi = (__nv_bfloat16*)(dsm + OFF_AHI);
    __nv_bfloat16* sAlo = (__nv_bfloat16*)(dsm + OFF_ALO);
    int*           sX   = (int*)(dsm + OFF_X);

    const int tid = threadIdx.x, bid = blockIdx.x;
    const int g   = bid / NTL;          // batch group 0..3
    const int ntl = bid % NTL;          // 0..32 (32 = logits tile)
    const int gbase = g * BG;
    const int ncol0 = ntl * NSL;        // global N col base (1024 for logits)
    const int lane = tid & 31, w = tid >> 5;    // 8 warps
    const int mt = w & 1, nq = w >> 1;  // m-tile (16 rows), n-quad (8 cols)
    const int gq = lane >> 2, tg = lane & 3;
    const int r0 = mt * 16 + gq, r1 = r0 + 8;
    const int c0 = nq * 8 + tg * 2;     // local col

    unsigned tokA = acqload(&g_cnt_all);
    unsigned tokG = acqload(&g_cntg[g * 8]);

    // ======== prologue ========
    // W^T hi/lo split: CTA owns rows n in [bid*8, bid*8+8)  (132*8 = 1056)
    for (int k2 = tid; k2 < Hn; k2 += NT) {
#pragma unroll
        for (int j = 0; j < 8; ++j) {
            int n = bid * 8 + j;
            float wv = (n < Hn) ? Wh[k2 * Hn + n] : Wo[k2 * Vn + (n - Hn)];
            unsigned short hi, lo; pack_hilo(wv, hi, lo);
            g_WT_hi[n * Hn + k2] = __ushort_as_bfloat16(hi);
            g_WT_lo[n * Hn + k2] = __ushort_as_bfloat16(lo);
        }
    }
    {
        int e = bid * NT + tid;
        if (e < Vn * Hn) {
            int v = e >> 10, h = e & 1023;
            float acc = bh[h];
            const float* er = emb + v * En;
#pragma unroll 8
            for (int q = 0; q < En; ++q) acc = fmaf(er[q], We[q * Hn + h], acc);
            g_P[e] = acc;
        }
    }
    if (bid < Bn) {
        int i0 = bid * Hn + tid * 4;
        float4 hv = *(const float4*)(hidden + i0);
        float vv[4] = {hv.x, hv.y, hv.z, hv.w};
        unsigned short uh[4], ul[4];
#pragma unroll
        for (int j = 0; j < 4; ++j) pack_hilo(vv[j], uh[j], ul[j]);
        *(uint2*)(&g_hbf_hi[0][i0]) = make_uint2(uh[0] | (uh[1] << 16), uh[2] | (uh[3] << 16));
        *(uint2*)(&g_hbf_lo[0][i0]) = make_uint2(ul[0] | (ul[1] << 16), ul[2] | (ul[3] << 16));
    }
    // prologue barrier: all 132 CTAs
    __syncthreads();
    if (tid == 0) arrive(&g_cnt_all);
    tokA += G;
    if (tid == 0) waitcnt(&g_cnt_all, tokA);
    __syncthreads();

    // persistent B tile: 32 n-rows x 1024 k (hi + lo)
    for (int idx = tid; idx < (NSL * Hn) / 8; idx += NT) {
        int i = idx * 8;
        int n = i >> 10, k = i & 1023;
        *(uint4*)(sBhi + n * PB + k) = *(const uint4*)(&g_WT_hi[(ncol0 + n) * Hn + k]);
        *(uint4*)(sBlo + n * PB + k) = *(const uint4*)(&g_WT_lo[(ncol0 + n) * Hn + k]);
    }

    // fragment base addresses (bytes)
    const uint32_t aHiAddr = smem_u32(sAhi) +
        (uint32_t)(((mt * 16 + (lane & 7) + ((lane >> 3) & 1) * 8) * PA + (lane >> 4) * 8) * 2);
    const uint32_t aLoAddr = aHiAddr + (uint32_t)(OFF_ALO - OFF_AHI);
    const uint32_t bHiAddr = smem_u32(sBhi) +
        (uint32_t)(((nq * 8 + (lane & 7)) * PB + (lane >> 3) * 8) * 2);
    const uint32_t bLoAddr = bHiAddr + (uint32_t)OFF_BLO;

    // ======== recurrence: iter l consumes h_l -> h_{l+1} (tiles 0..31) / logits[l-1] (tile 32)
    for (int l = 0; l <= Ln; ++l) {
        const int c = l & 1;
        const bool act = (l < Ln) || (ntl == NTL - 1);

        float acc0[4] = {0.f, 0.f, 0.f, 0.f};
        float acc1[4] = {0.f, 0.f, 0.f, 0.f};

        if (act) {
#pragma unroll
            for (int half = 0; half < 2; ++half) {
                __syncthreads();   // previous MMA reads of sA done
                // stage A half: 32 rows x 512 k (hi + lo), coalesced .cg
#pragma unroll
                for (int it = 0; it < 8; ++it) {
                    int i = (it * NT + tid) * 8;
                    int row = i >> 9, k = i & 511;
                    *(uint4*)(sAhi + row * PA + k) =
                        ldcg4(&g_hbf_hi[c][(gbase + row) * Hn + half * KH + k]);
                    *(uint4*)(sAlo + row * PA + k) =
                        ldcg4(&g_hbf_lo[c][(gbase + row) * Hn + half * KH + k]);
                }
                if (half == 0 && tid < BG && l < Ln)
                    sX[tid] = __ldg(&x[(gbase + tid) * Ln + l]);
                __syncthreads();

                const uint32_t bh4 = (uint32_t)(half * KH * 2);
#pragma unroll
                for (int kp = 0; kp < 16; ++kp) {
                    const uint32_t ko = (uint32_t)(kp * 64);   // 32 k-elems = 64B
                    uint32_t ah0, ah1, ah2, ah3, ag0, ag1, ag2, ag3;
                    LDSM4(ah0, ah1, ah2, ah3, aHiAddr + ko);
                    LDSM4(ag0, ag1, ag2, ag3, aHiAddr + ko + 32);
                    uint32_t al0, al1, al2, al3, am0, am1, am2, am3;
                    LDSM4(al0, al1, al2, al3, aLoAddr + ko);
                    LDSM4(am0, am1, am2, am3, aLoAddr + ko + 32);
                    uint32_t b0, b1, b2, b3, e0, e1, e2, e3;
                    LDSM4(b0, b1, b2, b3, bHiAddr + bh4 + ko);
                    LDSM4(e0, e1, e2, e3, bLoAddr + bh4 + ko);

                    MMA16816(acc0, ah0, ah1, ah2, ah3, b0, b1);
                    MMA16816(acc1, ag0, ag1, ag2, ag3, b2, b3);
                    MMA16816(acc0, ah0, ah1, ah2, ah3, e0, e1);
                    MMA16816(acc1, ag0, ag1, ag2, ag3, e2, e3);
                    MMA16816(acc0, al0, al1, al2, al3, b0, b1);
                    MMA16816(acc1, am0, am1, am2, am3, b2, b3);
                }
            }

            float p0 = acc0[0] + acc1[0], p1 = acc0[1] + acc1[1];
            float p2 = acc0[2] + acc1[2], p3 = acc0[3] + acc1[3];

            if (ntl < NTL - 1) {
                // h producer: + P[x], tanh, pack hi/lo
                const int xv0 = sX[r0], xv1 = sX[r1];
                float2 P0 = *(const float2*)(&g_P[xv0 * Hn + ncol0 + c0]);
                float2 P1 = *(const float2*)(&g_P[xv1 * Hn + ncol0 + c0]);
                float h00 = fast_tanh(p0 + P0.x), h01 = fast_tanh(p1 + P0.y);
                float h10 = fast_tanh(p2 + P1.x), h11 = fast_tanh(p3 + P1.y);
                unsigned short a_, b_, cq, d_, eq, f_, gg, hh;
                pack_hilo(h00, a_, b_); pack_hilo(h01, cq, d_);
                pack_hilo(h10, eq, f_); pack_hilo(h11, gg, hh);
                int i00 = (gbase + r0) * Hn + ncol0 + c0;
                int i10 = (gbase + r1) * Hn + ncol0 + c0;
                *(uint32_t*)(&g_hbf_hi[1 - c][i00]) = (uint32_t)a_ | ((uint32_t)cq << 16);
                *(uint32_t*)(&g_hbf_lo[1 - c][i00]) = (uint32_t)b_ | ((uint32_t)d_ << 16);
                *(uint32_t*)(&g_hbf_hi[1 - c][i10]) = (uint32_t)eq | ((uint32_t)gg << 16);
                *(uint32_t*)(&g_hbf_lo[1 - c][i10]) = (uint32_t)f_ | ((uint32_t)hh << 16);
                if (l == Ln - 1) {
                    *(float2*)(&outh[i00]) = make_float2(h00, h01);
                    *(float2*)(&outh[i10]) = make_float2(h10, h11);
                }
            } else if (l > 0) {
                // logits tile: + b_o, write logits[l-1]
                float2 B0 = *(const float2*)(&bo[c0]);
                *(float2*)(&logits[((size_t)(gbase + r0) * Ln + (l - 1)) * Vn + c0]) =
                    make_float2(p0 + B0.x, p1 + B0.y);
                *(float2*)(&logits[((size_t)(gbase + r1) * Ln + (l - 1)) * Vn + c0]) =
                    make_float2(p2 + B0.x, p3 + B0.y);
            }
        }

        // ---- per-group barrier (1 per step) ----
        if (l < Ln) {
            __syncthreads();
            if (tid == 0) arrive(&g_cntg[g * 8]);
            tokG += NTL;
            if (tid == 0) waitcnt(&g_cntg[g * 8], tokG);
            __syncthreads();
        }
    }
}

extern "C" void kernel_launch(void* const* d_in, const int* in_sizes, int n_in,
                              void* d_out, int out_size) {
    const int*   x      = (const int*)d_in[0];
    const float* hidden = (const float*)d_in[1];
    const float* emb    = (const float*)d_in[2];
    const float* We     = (const float*)d_in[3];
    const float* Wh     = (const float*)d_in[4];
    const float* bh     = (const float*)d_in[5];
    const float* Wo     = (const float*)d_in[6];
    const float* bo     = (const float*)d_in[7];

    float* logits = (float*)d_out;
    float* outh   = logits + (size_t)Bn * Ln * Vn;

    cudaFuncSetAttribute(rnn_all,
                         cudaFuncAttributeMaxDynamicSharedMemorySize, SMEM_BYTES);
    rnn_all<<<G, NT, SMEM_BYTES>>>(x, hidden, emb, We, Wh, bh, Wo, bo, logits, outh);
}

// round 10
// speedup vs baseline: 2.0606x; 1.3587x over previous
#include <cuda_runtime.h>
#include <cuda_bf16.h>
#include <stdint.h>
#include <math.h>

#define Bn 128
#define Ln 1024
#define Vn 32
#define En 256
#define Hn 1024
#define NTOT 1056        // Hn + Vn (W_o folded)

#define NG  4            // independent batch groups
#define BG  32           // batch rows per group
#define NTL 33           // CTAs per group (32 h-tiles + 1 logits tile)
#define NSL 32           // N cols per CTA
#define G   (NG * NTL)   // 132 persistent CTAs
#define NT  256          // 8 warps
#define KW  128          // K columns per warp (8 warps x 128 = 1024)
#define PA  1032         // A smem pitch (bf16): 2064B stride -> LDSM conflict-free
#define PN  36           // reduction pitch (floats)

// ---------------- device scratch ----------------
__device__ float         g_P[Vn * Hn];
__device__ __nv_bfloat16 g_hbf_hi[2][Bn * Hn];
__device__ __nv_bfloat16 g_hbf_lo[2][Bn * Hn];
__device__ __nv_bfloat16 g_WT_hi[NTOT * Hn];   // [n][k]
__device__ __nv_bfloat16 g_WT_lo[NTOT * Hn];
__device__ unsigned      g_cnt_all;            // prologue barrier (all G)
__device__ unsigned      g_cntg[NG * 8];       // per-group step counters (padded)

// smem layout (bytes):
//  sAhi : 0      .. 66048   (32 x PA bf16)
//  sAlo : 66048  .. 132096
//  sRed : 132096 .. 168960  (8 x 32 x PN floats)
//  sX   : 168960 .. 169088
#define OFF_ALO 66048
#define OFF_RED 132096
#define OFF_X   168960
#define SMEM_BYTES 169088
#define A_MT (16 * PA * 2)   // byte offset between m-tiles

// ---------------- helpers ----------------
#define MMA16816(d, a0, a1, a2, a3, b0, b1) \
    asm volatile("mma.sync.aligned.m16n8k16.row.col.f32.bf16.bf16.f32 " \
        "{%0,%1,%2,%3}, {%4,%5,%6,%7}, {%8,%9}, {%0,%1,%2,%3};" \
        : "+f"((d)[0]), "+f"((d)[1]), "+f"((d)[2]), "+f"((d)[3]) \
        : "r"(a0), "r"(a1), "r"(a2), "r"(a3), "r"(b0), "r"(b1))

#define LDSM4(r0, r1, r2, r3, addr) \
    asm volatile("ldmatrix.sync.aligned.m8n8.x4.shared.b16 {%0,%1,%2,%3}, [%4];" \
        : "=r"(r0), "=r"(r1), "=r"(r2), "=r"(r3) : "r"(addr))

__device__ __forceinline__ uint32_t smem_u32(const void* p) {
    uint32_t a;
    asm("{ .reg .u64 t; cvta.to.shared.u64 t, %1; cvt.u32.u64 %0, t; }"
        : "=r"(a) : "l"(p));
    return a;
}
__device__ __forceinline__ unsigned acqload(const unsigned* p) {
    unsigned v;
    asm volatile("ld.acquire.gpu.u32 %0, [%1];" : "=r"(v) : "l"(p) : "memory");
    return v;
}
__device__ __forceinline__ void arrive(unsigned* cnt) {
    asm volatile("red.release.gpu.global.add.u32 [%0], 1;" :: "l"(cnt) : "memory");
}
__device__ __forceinline__ void waitcnt(unsigned* cnt, unsigned target) {
    unsigned v = acqload(cnt);
    while ((int)(v - target) < 0) v = acqload(cnt);
}
__device__ __forceinline__ uint4 ldcg4(const void* p) {
    uint4 r;
    asm volatile("ld.global.cg.v4.u32 {%0,%1,%2,%3}, [%4];"
        : "=r"(r.x), "=r"(r.y), "=r"(r.z), "=r"(r.w) : "l"(p));
    return r;
}
__device__ __forceinline__ void pack_hilo(float v, unsigned short& hi, unsigned short& lo) {
    __nv_bfloat16 hb = __float2bfloat16(v);
    hi = __bfloat16_as_ushort(hb);
    lo = __bfloat16_as_ushort(__float2bfloat16(v - __bfloat162float(hb)));
}
__device__ __forceinline__ float fast_tanh(float x) {
    float e = __expf(2.0f * x);
    return 1.0f - __fdividef(2.0f, e + 1.0f);
}

// ---------------- the single persistent kernel ----------------
__global__ void __launch_bounds__(NT, 1)
rnn_all(const int* __restrict__ x, const float* __restrict__ hidden,
        const float* __restrict__ emb, const float* __restrict__ We,
        const float* __restrict__ Wh, const float* __restrict__ bh,
        const float* __restrict__ Wo, const float* __restrict__ bo,
        float* __restrict__ logits, float* __restrict__ outh) {
    extern __shared__ __align__(16) char dsm[];
    __nv_bfloat16* sAhi = (__nv_bfloat16*)dsm;
    __nv_bfloat16* sAlo = (__nv_bfloat16*)(dsm + OFF_ALO);
    float*         sRed = (float*)(dsm + OFF_RED);
    int*           sX   = (int*)(dsm + OFF_X);

    const int tid = threadIdx.x, bid = blockIdx.x;
    const int g     = bid / NTL;        // batch group 0..3
    const int ntl   = bid % NTL;        // 0..32 (32 = logits tile)
    const int gbase = g * BG;
    const int ncol0 = ntl * NSL;        // global N col base (1024 = logits)
    const int lane = tid & 31, w = tid >> 5;
    const int gq = lane >> 2, tg = lane & 3;
    const int kw = w * KW;              // this warp's k-slice base

    unsigned tokA = acqload(&g_cnt_all);
    unsigned tokG = acqload(&g_cntg[g * 8]);

    // ======== prologue ========
    for (int k2 = tid; k2 < Hn; k2 += NT) {
#pragma unroll
        for (int j = 0; j < 8; ++j) {
            int n = bid * 8 + j;
            float wv = (n < Hn) ? Wh[k2 * Hn + n] : Wo[k2 * Vn + (n - Hn)];
            unsigned short hi, lo; pack_hilo(wv, hi, lo);
            g_WT_hi[n * Hn + k2] = __ushort_as_bfloat16(hi);
            g_WT_lo[n * Hn + k2] = __ushort_as_bfloat16(lo);
        }
    }
    {
        int e = bid * NT + tid;
        if (e < Vn * Hn) {
            int v = e >> 10, h = e & 1023;
            float acc = bh[h];
            const float* er = emb + v * En;
#pragma unroll 8
            for (int q = 0; q < En; ++q) acc = fmaf(er[q], We[q * Hn + h], acc);
            g_P[e] = acc;
        }
    }
    if (bid < Bn) {
        int i0 = bid * Hn + tid * 4;
        float4 hv = *(const float4*)(hidden + i0);
        float vv[4] = {hv.x, hv.y, hv.z, hv.w};
        unsigned short uh[4], ul[4];
#pragma unroll
        for (int j = 0; j < 4; ++j) pack_hilo(vv[j], uh[j], ul[j]);
        *(uint2*)(&g_hbf_hi[0][i0]) = make_uint2(uh[0] | (uh[1] << 16), uh[2] | (uh[3] << 16));
        *(uint2*)(&g_hbf_lo[0][i0]) = make_uint2(ul[0] | (ul[1] << 16), ul[2] | (ul[3] << 16));
    }
    // prologue barrier (all 132 CTAs; R7-style leader spin)
    __syncthreads();
    if (tid == 0) arrive(&g_cnt_all);
    tokA += G;
    if (tid == 0) waitcnt(&g_cnt_all, tokA);
    __syncthreads();

    // ======== B-fragment setup: stage B tile once, LDSM into registers ========
    uint32_t Bh[8][4][2], Bl[8][4][2];
    {
        // stage B rows (hi -> sAhi, lo -> sAlo), n local rows 0..31, k 0..1023
#pragma unroll
        for (int it = 0; it < 16; ++it) {
            int i = (it * NT + tid) * 8;
            int n = i >> 10, k = i & 1023;
            *(uint4*)(sAhi + n * PA + k) = *(const uint4*)(&g_WT_hi[(ncol0 + n) * Hn + k]);
            *(uint4*)(sAlo + n * PA + k) = *(const uint4*)(&g_WT_lo[(ncol0 + n) * Hn + k]);
        }
        __syncthreads();
        const uint32_t bBase = smem_u32(sAhi) +
            (uint32_t)(2 * ((lane & 7) * PA + kw + ((lane >> 3) & 1) * 8));
#pragma unroll
        for (int nb2 = 0; nb2 < 2; ++nb2) {
            const uint32_t ba = bBase + (uint32_t)(2 * (nb2 * 2 + (lane >> 4)) * 8 * PA);
#pragma unroll
            for (int ks = 0; ks < 8; ++ks) {
                LDSM4(Bh[ks][nb2 * 2][0], Bh[ks][nb2 * 2][1],
                      Bh[ks][nb2 * 2 + 1][0], Bh[ks][nb2 * 2 + 1][1], ba + ks * 32);
                LDSM4(Bl[ks][nb2 * 2][0], Bl[ks][nb2 * 2][1],
                      Bl[ks][nb2 * 2 + 1][0], Bl[ks][nb2 * 2 + 1][1],
                      ba + ks * 32 + (uint32_t)OFF_ALO);
            }
        }
        __syncthreads();
    }

    // A fragment base (this warp's k-slice)
    const uint32_t aHiAddr = smem_u32(sAhi) +
        (uint32_t)(2 * (((lane & 7) + ((lane >> 3) & 1) * 8) * PA + kw + (lane >> 4) * 8));
    const uint32_t aLoAddr = aHiAddr + (uint32_t)OFF_ALO;

    // ======== recurrence ========
    for (int l = 0; l <= Ln; ++l) {
        const int c = l & 1;
        const bool act = (l < Ln) || (ntl == NTL - 1);

        if (act) {   // stage A: 32 rows x 1024 k, hi+lo, L2-only loads
#pragma unroll
            for (int it = 0; it < 16; ++it) {
                int i = (it * NT + tid) * 8;
                int row = i >> 10, k = i & 1023;
                *(uint4*)(sAhi + row * PA + k) = ldcg4(&g_hbf_hi[c][(gbase + row) * Hn + k]);
            }
#pragma unroll
            for (int it = 0; it < 16; ++it) {
                int i = (it * NT + tid) * 8;
                int row = i >> 10, k = i & 1023;
                *(uint4*)(sAlo + row * PA + k) = ldcg4(&g_hbf_lo[c][(gbase + row) * Hn + k]);
            }
        }
        if (l < Ln && tid < BG) sX[tid] = __ldg(&x[(gbase + tid) * Ln + l]);
        __syncthreads();

        if (act) {
            float acc[2][4][4];
#pragma unroll
            for (int mt = 0; mt < 2; ++mt)
#pragma unroll
                for (int nb = 0; nb < 4; ++nb)
#pragma unroll
                    for (int q = 0; q < 4; ++q) acc[mt][nb][q] = 0.f;

#pragma unroll
            for (int mt = 0; mt < 2; ++mt) {
                const uint32_t mo = (uint32_t)(mt * A_MT);
#pragma unroll
                for (int ks = 0; ks < 8; ++ks) {
                    uint32_t ah0, ah1, ah2, ah3, al0, al1, al2, al3;
                    LDSM4(ah0, ah1, ah2, ah3, aHiAddr + mo + ks * 32);
                    LDSM4(al0, al1, al2, al3, aLoAddr + mo + ks * 32);
#pragma unroll
                    for (int nb = 0; nb < 4; ++nb) {
                        MMA16816(acc[mt][nb], ah0, ah1, ah2, ah3, Bh[ks][nb][0], Bh[ks][nb][1]);
                        MMA16816(acc[mt][nb], ah0, ah1, ah2, ah3, Bl[ks][nb][0], Bl[ks][nb][1]);
                        MMA16816(acc[mt][nb], al0, al1, al2, al3, Bh[ks][nb][0], Bh[ks][nb][1]);
                    }
                }
            }
            // store per-warp partials (k-slice sums) to smem
            float* rp = sRed + w * 32 * PN;
#pragma unroll
            for (int mt = 0; mt < 2; ++mt)
#pragma unroll
                for (int nb = 0; nb < 4; ++nb) {
                    int r0 = mt * 16 + gq, col = nb * 8 + tg * 2;
                    *(float2*)(rp + r0 * PN + col)       = make_float2(acc[mt][nb][0], acc[mt][nb][1]);
                    *(float2*)(rp + (r0 + 8) * PN + col) = make_float2(acc[mt][nb][2], acc[mt][nb][3]);
                }
        }
        __syncthreads();

        if (act) {
            // reduce 8 k-slices: thread owns row m, cols n0..n0+3
            const int m = tid >> 3, n0 = (tid & 7) * 4;
            float4 s = *(const float4*)(sRed + m * PN + n0);
#pragma unroll
            for (int j = 1; j < 8; ++j) {
                float4 p = *(const float4*)(sRed + j * 32 * PN + m * PN + n0);
                s.x += p.x; s.y += p.y; s.z += p.z; s.w += p.w;
            }
            if (ntl < NTL - 1) {
                if (l < Ln) {
                    const int xv = sX[m];
                    float4 Pv = *(const float4*)(&g_P[xv * Hn + ncol0 + n0]);
                    float h0 = fast_tanh(s.x + Pv.x), h1 = fast_tanh(s.y + Pv.y);
                    float h2 = fast_tanh(s.z + Pv.z), h3 = fast_tanh(s.w + Pv.w);
                    unsigned short uh[4], ul[4];
                    pack_hilo(h0, uh[0], ul[0]); pack_hilo(h1, uh[1], ul[1]);
                    pack_hilo(h2, uh[2], ul[2]); pack_hilo(h3, uh[3], ul[3]);
                    int i0 = (gbase + m) * Hn + ncol0 + n0;
                    *(uint2*)(&g_hbf_hi[1 - c][i0]) =
                        make_uint2(uh[0] | (uh[1] << 16), uh[2] | (uh[3] << 16));
                    *(uint2*)(&g_hbf_lo[1 - c][i0]) =
                        make_uint2(ul[0] | (ul[1] << 16), ul[2] | (ul[3] << 16));
                    if (l == Ln - 1)
                        *(float4*)(&outh[i0]) = make_float4(h0, h1, h2, h3);
                }
            } else if (l > 0) {
                float4 B0 = *(const float4*)(&bo[n0]);
                *(float4*)(&logits[((size_t)(gbase + m) * Ln + (l - 1)) * Vn + n0]) =
                    make_float4(s.x + B0.x, s.y + B0.y, s.z + B0.z, s.w + B0.w);
            }
        }

        // per-group barrier (1 per step)
        if (l < Ln) {
            __syncthreads();
            if (tid == 0) arrive(&g_cntg[g * 8]);
            tokG += NTL;
            if (tid == 0) waitcnt(&g_cntg[g * 8], tokG);
            __syncthreads();
        }
    }
}

extern "C" void kernel_launch(void* const* d_in, const int* in_sizes, int n_in,
                              void* d_out, int out_size) {
    const int*   x      = (const int*)d_in[0];
    const float* hidden = (const float*)d_in[1];
    const float* emb    = (const float*)d_in[2];
    const float* We     = (const float*)d_in[3];
    const float* Wh     = (const float*)d_in[4];
    const float* bh     = (const float*)d_in[5];
    const float* Wo     = (const float*)d_in[6];
    const float* bo     = (const float*)d_in[7];

    float* logits = (float*)d_out;
    float* outh   = logits + (size_t)Bn * Ln * Vn;

    cudaFuncSetAttribute(rnn_all,
                         cudaFuncAttributeMaxDynamicSharedMemorySize, SMEM_BYTES);
    rnn_all<<<G, NT, SMEM_BYTES>>>(x, hidden, emb, We, Wh, bh, Wo, bo, logits, outh);
}